// round 15
// baseline (speedup 1.0000x reference)
#include <cuda_runtime.h>
#include <stdint.h>

// ---------------------------------------------------------------------------
// DenseCRF mean-field (R11):
//   * separable spatial Gaussian; z-conv + y-conv fused in one smem pass
//   * color-sparse bilateral kernel (~17 nbrs/pixel), fused into same launch
//   * NO global sort: k_build sorts its staged segments in smem (bit-identical
//     candidate order); counters re-zeroed by last k_final (no memset nodes)
// ---------------------------------------------------------------------------

#define NPIX   8192
#define DD     8
#define LL     21
#define LP     24
#define NITER  5
#define NBIN   12
#define NBIN3  1728
#define CAP    128
#define SCAP   1024
#define ECUT   23.0f

#define SA (1.0f/(160.0f*1.41421356237f))
#define SB (1.0f/(3.0f*1.41421356237f))

// ------------------------------- scratch -----------------------------------
__device__ float4 g_col[NPIX];
__device__ int    g_binid[NPIX];
__device__ int    g_binstart[NBIN3];
__device__ int    g_bincnt[NBIN3];        // zero at load; re-zeroed each run
__device__ int    g_bincur[NBIN3];        // zero at load; re-zeroed each run
__device__ int    g_binpts[NPIX];
__device__ float2 g_nn[NPIX*CAP];     // (.x = bitcast idx, .y = kernel value)
__device__ int    g_ncnt[NPIX];
__device__ float  g_nbi[NPIX];
__device__ float  g_qT[NPIX*LP];
__device__ float  g_uT[NPIX*LP];      // unary transposed, pixel-major
__device__ float  g_t2[NPIX*LP];      // after z+y conv
__device__ float  g_bi[NPIX*LP];
__device__ float  g_CWsp[LL*LL];
__device__ float  g_CWbi[LL*LL];
__device__ float  g_kg[32*32];
__device__ float  g_sz[8];
__device__ float  g_syx[32];

// ---------------------------------------------------------------------------
// k_prep: blocks [0,64) per-pixel work; block 64 = CW matrices + LUTs.
// ---------------------------------------------------------------------------
__global__ void k_prep(const float* __restrict__ image,
                       const float* __restrict__ logits,
                       const float* __restrict__ unary,
                       const float* __restrict__ Wsp,
                       const float* __restrict__ Wbi,
                       const float* __restrict__ C)
{
    if (blockIdx.x == 64) {
        int tid = threadIdx.x;                 // 128
        for (int e = tid; e < LL*LL; e += 128) {
            int l = e / LL, m = e - l*LL;
            float a = 0.f, b = 0.f;
            for (int k = 0; k < LL; k++) {
                float c = C[l*LL + k];
                a += c * Wsp[k*LL + m];
                b += c * Wbi[k*LL + m];
            }
            g_CWsp[e] = a; g_CWbi[e] = b;
        }
        for (int e = tid; e < 1024; e += 128) {
            int a = e >> 5, b = e & 31;
            float d = (float)(a - b) * (1.0f/3.0f);
            g_kg[e] = __expf(-0.5f * d * d);
        }
        if (tid < 32) {
            float s = 0.f;
            for (int b = 0; b < 32; b++) { float d = (float)(tid-b)*(1.0f/3.0f); s += __expf(-0.5f*d*d); }
            g_syx[tid] = s;
        } else if (tid < 40) {
            int a = tid - 32; float s = 0.f;
            for (int b = 0; b < 8; b++) { float d = (float)(a-b)*(1.0f/3.0f); s += __expf(-0.5f*d*d); }
            g_sz[a] = s;
        }
        return;
    }

    int i = blockIdx.x * blockDim.x + threadIdx.x;    // 8192
    float c0 = image[i], c1 = image[NPIX + i], c2 = image[2*NPIX + i];
    g_col[i] = make_float4(c0*SB, c1*SB, c2*SB, 0.f);
    int b0 = (int)(c0 * (12.0f/255.0f)); b0 = b0 < 0 ? 0 : (b0 > 11 ? 11 : b0);
    int b1 = (int)(c1 * (12.0f/255.0f)); b1 = b1 < 0 ? 0 : (b1 > 11 ? 11 : b1);
    int b2 = (int)(c2 * (12.0f/255.0f)); b2 = b2 < 0 ? 0 : (b2 > 11 ? 11 : b2);
    int bin = (b0*NBIN + b1)*NBIN + b2;
    g_binid[i] = bin;
    atomicAdd(&g_bincnt[bin], 1);

    float v[LL]; float mx = -1e30f;
    #pragma unroll
    for (int l = 0; l < LL; l++) { v[l] = logits[l*NPIX + i]; mx = fmaxf(mx, v[l]); }
    float s = 0.f;
    #pragma unroll
    for (int l = 0; l < LL; l++) { v[l] = __expf(v[l] - mx); s += v[l]; }
    float inv = 1.0f / s;
    #pragma unroll
    for (int l = 0; l < LL; l++) g_qT[i*LP + l] = v[l] * inv;
    g_qT[i*LP + 21] = 0.f; g_qT[i*LP + 22] = 0.f; g_qT[i*LP + 23] = 0.f;

    #pragma unroll
    for (int l = 0; l < LL; l++) g_uT[i*LP + l] = unary[l*NPIX + i];
}

// ---------------------------------------------------------------------------
// k_scan: prefix sum over 1728 bin counts (single block).
// ---------------------------------------------------------------------------
__global__ void k_scan()
{
    __shared__ int scnt[NBIN3];
    __shared__ int csum[28];
    const int tid = threadIdx.x;                 // 1024
    for (int e = tid; e < NBIN3; e += 1024) scnt[e] = g_bincnt[e];
    __syncthreads();
    if (tid < 27) {
        int s = 0;
        for (int k = 0; k < 64; k++) s += scnt[tid*64 + k];
        csum[tid] = s;
    }
    __syncthreads();
    if (tid == 0) {
        int s = 0;
        for (int c = 0; c < 27; c++) { int t = csum[c]; csum[c] = s; s += t; }
    }
    __syncthreads();
    for (int b = tid; b < NBIN3; b += 1024) {
        int chunk = b >> 6;
        int s = csum[chunk];
        for (int k = chunk*64; k < b; k++) s += scnt[k];
        g_binstart[b] = s;
    }
}

// ---------------------------------------------------------------------------
__global__ void k_scatter()
{
    int i = blockIdx.x * blockDim.x + threadIdx.x;    // 8192
    int b = g_binid[i];
    int off = atomicAdd(&g_bincur[b], 1);
    g_binpts[g_binstart[b] + off] = i;
}

// ---------------------------------------------------------------------------
// Build sparse bilateral rows per bin. 256 threads, 17KB smem.
// Staged candidate segments are sorted ascending in smem -> deterministic,
// bit-identical to a globally sorted CSR.
// ---------------------------------------------------------------------------
__global__ void k_build()
{
    __shared__ int   sj[SCAP];
    __shared__ float s0[SCAP], s1[SCAP], s2[SCAP];
    __shared__ int   nstart[27], npre[28];
    const int tid = threadIdx.x;                       // 256
    const int b   = blockIdx.x;
    const int cnt = g_bincnt[b];
    if (cnt == 0) return;

    int b0 = b / 144, r = b - b0*144, b1 = r / 12, b2 = r - b1*12;
    int d0lo = b0 > 0 ? b0-1 : 0, d0hi = b0 < 11 ? b0+1 : 11;
    int d1lo = b1 > 0 ? b1-1 : 0, d1hi = b1 < 11 ? b1+1 : 11;
    int d2lo = b2 > 0 ? b2-1 : 0, d2hi = b2 < 11 ? b2+1 : 11;
    int n0 = d0hi-d0lo+1, n1 = d1hi-d1lo+1, n2 = d2hi-d2lo+1;
    int nseg = n0*n1*n2;                               // <= 27

    if (tid < nseg) {
        int q = tid;
        int e0 = q / (n1*n2); q -= e0*(n1*n2);
        int e1 = q / n2, e2 = q - e1*n2;
        int nbin = ((d0lo+e0)*NBIN + (d1lo+e1))*NBIN + (d2lo+e2);
        nstart[tid] = g_binstart[nbin];
        npre[tid]   = g_bincnt[nbin];
    }
    __syncthreads();
    if (tid == 0) {
        int s = 0;
        for (int k = 0; k < nseg; k++) { int c = npre[k]; npre[k] = s; s += c; }
        npre[nseg] = s;
    }
    __syncthreads();
    int tot = npre[nseg]; if (tot > SCAP) tot = SCAP;

    // stage indices
    for (int idx = tid; idx < tot; idx += 256) {
        int seg = 0;
        while (seg + 1 < nseg && npre[seg + 1] <= idx) seg++;
        sj[idx] = g_binpts[nstart[seg] + (idx - npre[seg])];
    }
    __syncthreads();

    const int lane = tid & 31;
    const int w    = tid >> 5;                         // 8 warps

    // sort each segment ascending (warp rank sort; rare >32 serial fallback)
    for (int seg = w; seg < nseg; seg += 8) {
        int ss = npre[seg];
        int se = npre[seg + 1] < tot ? npre[seg + 1] : tot;
        int len = se - ss;
        if (len <= 1) continue;
        if (len <= 32) {
            int v = (lane < len) ? sj[ss + lane] : 0x7fffffff;
            int rank = 0;
            #pragma unroll
            for (int o = 0; o < 32; o++) {
                int u = __shfl_sync(0xffffffffu, v, o);
                rank += (u < v) || (u == v && o < lane);
            }
            __syncwarp();
            if (lane < len) sj[ss + rank] = v;
            __syncwarp();
        } else if (lane == 0) {
            for (int a = 1; a < len; a++) {
                int v = sj[ss + a]; int k = a - 1;
                while (k >= 0 && sj[ss + k] > v) { sj[ss + k + 1] = sj[ss + k]; k--; }
                sj[ss + k + 1] = v;
            }
        }
    }
    __syncthreads();

    // fetch colors in sorted order
    for (int idx = tid; idx < tot; idx += 256) {
        float4 col = g_col[sj[idx]];
        s0[idx] = col.x; s1[idx] = col.y; s2[idx] = col.z;
    }
    __syncthreads();

    const int mybase = g_binstart[b];
    const int pos = tot;

    for (int p = w; p < cnt; p += 8) {
        int i = g_binpts[mybase + p];
        float4 ci = g_col[i];
        int iz = i >> 10, iy = (i >> 5) & 31, ix = i & 31;
        int   acc = 0;
        float nb  = 0.f;
        for (int base = 0; base < pos; base += 32) {
            int idx = base + lane;
            float ev = 1e30f; int j = 0;
            if (idx < pos) {
                j = sj[idx];
                float dz = (float)(iz - (j >> 10));
                float dy = (float)(iy - ((j >> 5) & 31));
                float dx = (float)(ix - (j & 31));
                float u3 = ci.x - s0[idx];
                float u4 = ci.y - s1[idx];
                float u5 = ci.z - s2[idx];
                ev = (dz*dz + dy*dy + dx*dx) * (SA*SA) + u3*u3 + u4*u4 + u5*u5;
            }
            bool a = (ev <= ECUT);
            unsigned m = __ballot_sync(0xffffffffu, a);
            if (a) {
                int off = acc + __popc(m & ((1u << lane) - 1u));
                if (off < CAP) {
                    float kv = __expf(-ev);
                    g_nn[i*CAP + off] = make_float2(__int_as_float(j), kv);
                    nb += kv;
                }
            }
            acc += __popc(m);
        }
        for (int o = 16; o; o >>= 1) nb += __shfl_xor_sync(0xffffffffu, nb, o);
        if (acc > CAP) acc = CAP;
        if (lane == 0) { g_ncnt[i] = acc; g_nbi[i] = nb; }
    }
}

// ---------------------------------------------------------------------------
// Iteration part A (one launch):
//   blocks [0,256):    fused z-conv + y-conv for one (z,x) column -> g_t2
//   blocks [256,598):  sparse bilateral gather (24 warps = 24 pixels each)
// ---------------------------------------------------------------------------
__global__ void k_iterA()
{
    if (blockIdx.x < 256) {
        __shared__ float t1s[32*LP];
        int z = blockIdx.x >> 5, x = blockIdx.x & 31;
        int tid = threadIdx.x;                 // 768
        int y = tid / LP, l = tid - y*LP;
        int i = (z << 10) + (y << 5) + x;
        float a = 0.f;
        #pragma unroll
        for (int zp = 0; zp < DD; zp++)
            a += g_kg[z*32 + zp] * g_qT[(((zp << 10) | (y << 5) | x))*LP + l];
        t1s[tid] = a;
        __syncthreads();
        float a2 = 0.f;
        const float* kr = &g_kg[y*32];
        #pragma unroll 8
        for (int yp = 0; yp < 32; yp++) a2 += kr[yp] * t1s[yp*LP + l];
        g_t2[i*LP + l] = a2;
    } else {
        int w    = (blockIdx.x - 256) * 24 + (threadIdx.x >> 5);
        int lane = threadIdx.x & 31;
        if (w >= NPIX || lane >= LP) return;
        int cnt  = g_ncnt[w];
        const float2* pp = &g_nn[w*CAP];
        float acc = 0.f;
        int n = 0;
        for (; n + 4 <= cnt; n += 4) {
            float2 p0 = pp[n],   p1 = pp[n+1], p2 = pp[n+2], p3 = pp[n+3];
            float a0 = g_qT[__float_as_int(p0.x)*LP + lane];
            float a1 = g_qT[__float_as_int(p1.x)*LP + lane];
            float a2 = g_qT[__float_as_int(p2.x)*LP + lane];
            float a3 = g_qT[__float_as_int(p3.x)*LP + lane];
            acc += p0.y*a0; acc += p1.y*a1; acc += p2.y*a2; acc += p3.y*a3;
        }
        for (; n < cnt; n++) { float2 p = pp[n]; acc += p.y * g_qT[__float_as_int(p.x)*LP + lane]; }
        g_bi[w*LP + lane] = acc;
    }
}

// ---------------------------------------------------------------------------
// Iteration part B: x-conv + normalize + mixing + unary + softmax.
// Last iteration also re-zeroes the bin counters for the next replay.
// ---------------------------------------------------------------------------
__global__ void k_final(float* __restrict__ out, int last)
{
    __shared__ float sh[32*LP];
    __shared__ float sc[32*LP];
    __shared__ float wsp[LL*LL], wbi[LL*LL];
    int z = blockIdx.x >> 5, y = blockIdx.x & 31;
    int tid = threadIdx.x;                 // 768
    int x = tid / LP, l = tid - x*LP;
    for (int e = tid; e < LL*LL; e += 768) { wsp[e] = g_CWsp[e]; wbi[e] = g_CWbi[e]; }
    int i = (z << 10) + (y << 5) + x;
    sh[tid] = g_t2[i*LP + l];
    __syncthreads();

    float sp = 0.f;
    {
        const float* kr = &g_kg[x*32];
        #pragma unroll 8
        for (int xp = 0; xp < 32; xp++) sp += kr[xp] * sh[xp*LP + l];
    }
    float nsp = g_sz[z] * g_syx[y] * g_syx[x];
    float nbi = g_nbi[i];
    __syncthreads();
    sh[tid] = sp / nsp;
    sc[tid] = g_bi[i*LP + l] / nbi;
    __syncthreads();

    float cur = -1e30f;
    if (l < LL) {
        float msg = 0.f;
        #pragma unroll
        for (int m = 0; m < LL; m++)
            msg += wsp[l*LL + m] * sh[x*LP + m] + wbi[l*LL + m] * sc[x*LP + m];
        cur = g_uT[i*LP + l] + msg;
    }
    __syncthreads();
    sh[tid] = cur;
    __syncthreads();

    float mx = -1e30f;
    #pragma unroll
    for (int m = 0; m < LL; m++) mx = fmaxf(mx, sh[x*LP + m]);
    float e = __expf(cur - mx);
    __syncthreads();
    sc[tid] = e;
    __syncthreads();
    float se = 0.f;
    #pragma unroll
    for (int m = 0; m < LL; m++) se += sc[x*LP + m];
    float q = e / se;
    g_qT[i*LP + l] = (l < LL) ? q : 0.f;
    if (last) {
        if (l < LL) out[l*NPIX + i] = q;
        int gt = blockIdx.x * 768 + tid;
        if (gt < NBIN3) { g_bincnt[gt] = 0; g_bincur[gt] = 0; }
    }
}

// ---------------------------------------------------------------------------
extern "C" void kernel_launch(void* const* d_in, const int* in_sizes, int n_in,
                              void* d_out, int out_size)
{
    (void)in_sizes; (void)n_in; (void)out_size;
    const float* image  = (const float*)d_in[0];
    const float* logits = (const float*)d_in[1];
    const float* unary  = (const float*)d_in[2];
    const float* Wsp    = (const float*)d_in[3];
    const float* Wbi    = (const float*)d_in[4];
    const float* C      = (const float*)d_in[5];
    float* out = (float*)d_out;

    k_prep<<<65, 128>>>(image, logits, unary, Wsp, Wbi, C);
    k_scan<<<1, 1024>>>();
    k_scatter<<<64, 128>>>();
    k_build<<<NBIN3, 256>>>();

    for (int it = 0; it < NITER; it++) {
        k_iterA<<<598, 768>>>();
        k_final<<<256, 768>>>(out, it == NITER - 1);
    }
}

// round 16
// speedup vs baseline: 1.0910x; 1.0910x over previous
#include <cuda_runtime.h>
#include <stdint.h>

// ---------------------------------------------------------------------------
// DenseCRF mean-field (R12 = R10 + memset-node removal):
//   * separable spatial Gaussian; z-conv + y-conv fused in one smem pass
//   * color-sparse bilateral kernel (~17 nbrs/pixel), fused into same launch
//   * warp-parallel per-bin rank sort (global, once per bin)
//   * counters re-zeroed by last k_final (no cudaMemsetAsync nodes)
// ---------------------------------------------------------------------------

#define NPIX   8192
#define DD     8
#define LL     21
#define LP     24
#define NITER  5
#define NBIN   12
#define NBIN3  1728
#define CAP    128
#define SCAP   1024
#define ECUT   23.0f

#define SA (1.0f/(160.0f*1.41421356237f))
#define SB (1.0f/(3.0f*1.41421356237f))

// ------------------------------- scratch -----------------------------------
__device__ float4 g_col[NPIX];
__device__ int    g_binid[NPIX];
__device__ int    g_binstart[NBIN3];
__device__ int    g_bincnt[NBIN3];        // zero at load; re-zeroed each run
__device__ int    g_bincur[NBIN3];        // zero at load; re-zeroed each run
__device__ int    g_binpts[NPIX];
__device__ float2 g_nn[NPIX*CAP];     // (.x = bitcast idx, .y = kernel value)
__device__ int    g_ncnt[NPIX];
__device__ float  g_nbi[NPIX];
__device__ float  g_qT[NPIX*LP];
__device__ float  g_uT[NPIX*LP];      // unary transposed, pixel-major
__device__ float  g_t2[NPIX*LP];      // after z+y conv
__device__ float  g_bi[NPIX*LP];
__device__ float  g_CWsp[LL*LL];
__device__ float  g_CWbi[LL*LL];
__device__ float  g_kg[32*32];
__device__ float  g_sz[8];
__device__ float  g_syx[32];

// ---------------------------------------------------------------------------
// k_prep: blocks [0,64) per-pixel work; block 64 = CW matrices + LUTs.
// ---------------------------------------------------------------------------
__global__ void k_prep(const float* __restrict__ image,
                       const float* __restrict__ logits,
                       const float* __restrict__ unary,
                       const float* __restrict__ Wsp,
                       const float* __restrict__ Wbi,
                       const float* __restrict__ C)
{
    if (blockIdx.x == 64) {
        int tid = threadIdx.x;                 // 128
        for (int e = tid; e < LL*LL; e += 128) {
            int l = e / LL, m = e - l*LL;
            float a = 0.f, b = 0.f;
            for (int k = 0; k < LL; k++) {
                float c = C[l*LL + k];
                a += c * Wsp[k*LL + m];
                b += c * Wbi[k*LL + m];
            }
            g_CWsp[e] = a; g_CWbi[e] = b;
        }
        for (int e = tid; e < 1024; e += 128) {
            int a = e >> 5, b = e & 31;
            float d = (float)(a - b) * (1.0f/3.0f);
            g_kg[e] = __expf(-0.5f * d * d);
        }
        if (tid < 32) {
            float s = 0.f;
            for (int b = 0; b < 32; b++) { float d = (float)(tid-b)*(1.0f/3.0f); s += __expf(-0.5f*d*d); }
            g_syx[tid] = s;
        } else if (tid < 40) {
            int a = tid - 32; float s = 0.f;
            for (int b = 0; b < 8; b++) { float d = (float)(a-b)*(1.0f/3.0f); s += __expf(-0.5f*d*d); }
            g_sz[a] = s;
        }
        return;
    }

    int i = blockIdx.x * blockDim.x + threadIdx.x;    // 8192
    float c0 = image[i], c1 = image[NPIX + i], c2 = image[2*NPIX + i];
    g_col[i] = make_float4(c0*SB, c1*SB, c2*SB, 0.f);
    int b0 = (int)(c0 * (12.0f/255.0f)); b0 = b0 < 0 ? 0 : (b0 > 11 ? 11 : b0);
    int b1 = (int)(c1 * (12.0f/255.0f)); b1 = b1 < 0 ? 0 : (b1 > 11 ? 11 : b1);
    int b2 = (int)(c2 * (12.0f/255.0f)); b2 = b2 < 0 ? 0 : (b2 > 11 ? 11 : b2);
    int bin = (b0*NBIN + b1)*NBIN + b2;
    g_binid[i] = bin;
    atomicAdd(&g_bincnt[bin], 1);

    float v[LL]; float mx = -1e30f;
    #pragma unroll
    for (int l = 0; l < LL; l++) { v[l] = logits[l*NPIX + i]; mx = fmaxf(mx, v[l]); }
    float s = 0.f;
    #pragma unroll
    for (int l = 0; l < LL; l++) { v[l] = __expf(v[l] - mx); s += v[l]; }
    float inv = 1.0f / s;
    #pragma unroll
    for (int l = 0; l < LL; l++) g_qT[i*LP + l] = v[l] * inv;
    g_qT[i*LP + 21] = 0.f; g_qT[i*LP + 22] = 0.f; g_qT[i*LP + 23] = 0.f;

    #pragma unroll
    for (int l = 0; l < LL; l++) g_uT[i*LP + l] = unary[l*NPIX + i];
}

// ---------------------------------------------------------------------------
// k_scan: prefix sum over 1728 bin counts (single block).
// ---------------------------------------------------------------------------
__global__ void k_scan()
{
    __shared__ int scnt[NBIN3];
    __shared__ int csum[28];
    const int tid = threadIdx.x;                 // 1024
    for (int e = tid; e < NBIN3; e += 1024) scnt[e] = g_bincnt[e];
    __syncthreads();
    if (tid < 27) {
        int s = 0;
        for (int k = 0; k < 64; k++) s += scnt[tid*64 + k];
        csum[tid] = s;
    }
    __syncthreads();
    if (tid == 0) {
        int s = 0;
        for (int c = 0; c < 27; c++) { int t = csum[c]; csum[c] = s; s += t; }
    }
    __syncthreads();
    for (int b = tid; b < NBIN3; b += 1024) {
        int chunk = b >> 6;
        int s = csum[chunk];
        for (int k = chunk*64; k < b; k++) s += scnt[k];
        g_binstart[b] = s;
    }
}

// ---------------------------------------------------------------------------
__global__ void k_scatter()
{
    int i = blockIdx.x * blockDim.x + threadIdx.x;    // 8192
    int b = g_binid[i];
    int off = atomicAdd(&g_bincur[b], 1);
    g_binpts[g_binstart[b] + off] = i;
}

// Warp-parallel per-bin rank sort -> deterministic ascending CSR order.
__global__ void k_sortbins()
{
    int warp = (blockIdx.x * blockDim.x + threadIdx.x) >> 5;   // bin
    int lane = threadIdx.x & 31;
    if (warp >= NBIN3) return;
    int s = g_binstart[warp];              // independent of the bincnt load
    int c = g_bincnt[warp];
    if (c <= 1) return;
    if (c <= 32) {
        int v = (lane < c) ? g_binpts[s + lane] : 0x7fffffff;
        int rank = 0;
        #pragma unroll
        for (int o = 0; o < 32; o++) {
            int u = __shfl_sync(0xffffffffu, v, o);
            rank += (u < v) || (u == v && o < lane);
        }
        if (lane < c) g_binpts[s + rank] = v;
    } else if (lane == 0) {       // rare huge bin: serial fallback
        for (int a = 1; a < c; a++) {
            int v = g_binpts[s + a]; int k = a - 1;
            while (k >= 0 && g_binpts[s + k] > v) { g_binpts[s + k + 1] = g_binpts[s + k]; k--; }
            g_binpts[s + k + 1] = v;
        }
    }
}

// ---------------------------------------------------------------------------
// Build sparse bilateral rows per bin. 256 threads, 17KB smem.
// ---------------------------------------------------------------------------
__global__ void k_build()
{
    __shared__ int   sj[SCAP];
    __shared__ float s0[SCAP], s1[SCAP], s2[SCAP];
    __shared__ int   nstart[27], npre[28];
    const int tid = threadIdx.x;                       // 256
    const int b   = blockIdx.x;
    const int cnt = g_bincnt[b];
    if (cnt == 0) return;

    int b0 = b / 144, r = b - b0*144, b1 = r / 12, b2 = r - b1*12;
    int d0lo = b0 > 0 ? b0-1 : 0, d0hi = b0 < 11 ? b0+1 : 11;
    int d1lo = b1 > 0 ? b1-1 : 0, d1hi = b1 < 11 ? b1+1 : 11;
    int d2lo = b2 > 0 ? b2-1 : 0, d2hi = b2 < 11 ? b2+1 : 11;
    int n0 = d0hi-d0lo+1, n1 = d1hi-d1lo+1, n2 = d2hi-d2lo+1;
    int nseg = n0*n1*n2;                               // <= 27

    if (tid < nseg) {
        int q = tid;
        int e0 = q / (n1*n2); q -= e0*(n1*n2);
        int e1 = q / n2, e2 = q - e1*n2;
        int nbin = ((d0lo+e0)*NBIN + (d1lo+e1))*NBIN + (d2lo+e2);
        nstart[tid] = g_binstart[nbin];
        npre[tid]   = g_bincnt[nbin];
    }
    __syncthreads();
    if (tid == 0) {
        int s = 0;
        for (int k = 0; k < nseg; k++) { int c = npre[k]; npre[k] = s; s += c; }
        npre[nseg] = s;
    }
    __syncthreads();
    int tot = npre[nseg]; if (tot > SCAP) tot = SCAP;

    for (int idx = tid; idx < tot; idx += 256) {
        int seg = 0;
        while (seg + 1 < nseg && npre[seg + 1] <= idx) seg++;
        int j = g_binpts[nstart[seg] + (idx - npre[seg])];
        float4 col = g_col[j];
        sj[idx] = j;
        s0[idx] = col.x; s1[idx] = col.y; s2[idx] = col.z;
    }
    __syncthreads();

    const int lane = tid & 31;
    const int w    = tid >> 5;                         // 8 warps
    const int mybase = g_binstart[b];
    const int pos = tot;

    for (int p = w; p < cnt; p += 8) {
        int i = g_binpts[mybase + p];
        float4 ci = g_col[i];
        int iz = i >> 10, iy = (i >> 5) & 31, ix = i & 31;
        int   acc = 0;
        float nb  = 0.f;
        for (int base = 0; base < pos; base += 32) {
            int idx = base + lane;
            float ev = 1e30f; int j = 0;
            if (idx < pos) {
                j = sj[idx];
                float dz = (float)(iz - (j >> 10));
                float dy = (float)(iy - ((j >> 5) & 31));
                float dx = (float)(ix - (j & 31));
                float u3 = ci.x - s0[idx];
                float u4 = ci.y - s1[idx];
                float u5 = ci.z - s2[idx];
                ev = (dz*dz + dy*dy + dx*dx) * (SA*SA) + u3*u3 + u4*u4 + u5*u5;
            }
            bool a = (ev <= ECUT);
            unsigned m = __ballot_sync(0xffffffffu, a);
            if (a) {
                int off = acc + __popc(m & ((1u << lane) - 1u));
                if (off < CAP) {
                    float kv = __expf(-ev);
                    g_nn[i*CAP + off] = make_float2(__int_as_float(j), kv);
                    nb += kv;
                }
            }
            acc += __popc(m);
        }
        for (int o = 16; o; o >>= 1) nb += __shfl_xor_sync(0xffffffffu, nb, o);
        if (acc > CAP) acc = CAP;
        if (lane == 0) { g_ncnt[i] = acc; g_nbi[i] = nb; }
    }
}

// ---------------------------------------------------------------------------
// Iteration part A (one launch):
//   blocks [0,256):    fused z-conv + y-conv for one (z,x) column -> g_t2
//   blocks [256,598):  sparse bilateral gather (24 warps = 24 pixels each)
// ---------------------------------------------------------------------------
__global__ void k_iterA()
{
    if (blockIdx.x < 256) {
        __shared__ float t1s[32*LP];
        int z = blockIdx.x >> 5, x = blockIdx.x & 31;
        int tid = threadIdx.x;                 // 768
        int y = tid / LP, l = tid - y*LP;
        int i = (z << 10) + (y << 5) + x;
        float a = 0.f;
        #pragma unroll
        for (int zp = 0; zp < DD; zp++)
            a += g_kg[z*32 + zp] * g_qT[(((zp << 10) | (y << 5) | x))*LP + l];
        t1s[tid] = a;
        __syncthreads();
        float a2 = 0.f;
        const float* kr = &g_kg[y*32];
        #pragma unroll 8
        for (int yp = 0; yp < 32; yp++) a2 += kr[yp] * t1s[yp*LP + l];
        g_t2[i*LP + l] = a2;
    } else {
        int w    = (blockIdx.x - 256) * 24 + (threadIdx.x >> 5);
        int lane = threadIdx.x & 31;
        if (w >= NPIX || lane >= LP) return;
        int cnt  = g_ncnt[w];
        const float2* pp = &g_nn[w*CAP];
        float acc = 0.f;
        int n = 0;
        for (; n + 4 <= cnt; n += 4) {
            float2 p0 = pp[n],   p1 = pp[n+1], p2 = pp[n+2], p3 = pp[n+3];
            float a0 = g_qT[__float_as_int(p0.x)*LP + lane];
            float a1 = g_qT[__float_as_int(p1.x)*LP + lane];
            float a2 = g_qT[__float_as_int(p2.x)*LP + lane];
            float a3 = g_qT[__float_as_int(p3.x)*LP + lane];
            acc += p0.y*a0; acc += p1.y*a1; acc += p2.y*a2; acc += p3.y*a3;
        }
        for (; n < cnt; n++) { float2 p = pp[n]; acc += p.y * g_qT[__float_as_int(p.x)*LP + lane]; }
        g_bi[w*LP + lane] = acc;
    }
}

// ---------------------------------------------------------------------------
// Iteration part B: x-conv + normalize + mixing + unary + softmax.
// Last iteration also re-zeroes the bin counters for the next replay.
// ---------------------------------------------------------------------------
__global__ void k_final(float* __restrict__ out, int last)
{
    __shared__ float sh[32*LP];
    __shared__ float sc[32*LP];
    __shared__ float wsp[LL*LL], wbi[LL*LL];
    int z = blockIdx.x >> 5, y = blockIdx.x & 31;
    int tid = threadIdx.x;                 // 768
    int x = tid / LP, l = tid - x*LP;
    for (int e = tid; e < LL*LL; e += 768) { wsp[e] = g_CWsp[e]; wbi[e] = g_CWbi[e]; }
    int i = (z << 10) + (y << 5) + x;
    sh[tid] = g_t2[i*LP + l];
    __syncthreads();

    float sp = 0.f;
    {
        const float* kr = &g_kg[x*32];
        #pragma unroll 8
        for (int xp = 0; xp < 32; xp++) sp += kr[xp] * sh[xp*LP + l];
    }
    float nsp = g_sz[z] * g_syx[y] * g_syx[x];
    float nbi = g_nbi[i];
    __syncthreads();
    sh[tid] = sp / nsp;
    sc[tid] = g_bi[i*LP + l] / nbi;
    __syncthreads();

    float cur = -1e30f;
    if (l < LL) {
        float msg = 0.f;
        #pragma unroll
        for (int m = 0; m < LL; m++)
            msg += wsp[l*LL + m] * sh[x*LP + m] + wbi[l*LL + m] * sc[x*LP + m];
        cur = g_uT[i*LP + l] + msg;
    }
    __syncthreads();
    sh[tid] = cur;
    __syncthreads();

    float mx = -1e30f;
    #pragma unroll
    for (int m = 0; m < LL; m++) mx = fmaxf(mx, sh[x*LP + m]);
    float e = __expf(cur - mx);
    __syncthreads();
    sc[tid] = e;
    __syncthreads();
    float se = 0.f;
    #pragma unroll
    for (int m = 0; m < LL; m++) se += sc[x*LP + m];
    float q = e / se;
    g_qT[i*LP + l] = (l < LL) ? q : 0.f;
    if (last) {
        if (l < LL) out[l*NPIX + i] = q;
        int gt = blockIdx.x * 768 + tid;
        if (gt < NBIN3) { g_bincnt[gt] = 0; g_bincur[gt] = 0; }
    }
}

// ---------------------------------------------------------------------------
extern "C" void kernel_launch(void* const* d_in, const int* in_sizes, int n_in,
                              void* d_out, int out_size)
{
    (void)in_sizes; (void)n_in; (void)out_size;
    const float* image  = (const float*)d_in[0];
    const float* logits = (const float*)d_in[1];
    const float* unary  = (const float*)d_in[2];
    const float* Wsp    = (const float*)d_in[3];
    const float* Wbi    = (const float*)d_in[4];
    const float* C      = (const float*)d_in[5];
    float* out = (float*)d_out;

    k_prep<<<65, 128>>>(image, logits, unary, Wsp, Wbi, C);
    k_scan<<<1, 1024>>>();
    k_scatter<<<64, 128>>>();
    k_sortbins<<<54, 1024>>>();
    k_build<<<NBIN3, 256>>>();

    for (int it = 0; it < NITER; it++) {
        k_iterA<<<598, 768>>>();
        k_final<<<256, 768>>>(out, it == NITER - 1);
    }
}